// round 2
// baseline (speedup 1.0000x reference)
#include <cuda_runtime.h>
#include <math.h>

#define Bsz 8
#define Cc 64
#define HWd 128
#define NPIX (HWd*HWd)
#define PLANE ((size_t)Cc*NPIX)
#define BS ((size_t)Bsz*Cc*NPIX)
#define LEAKv 0.2f
#define CLAMPv 0.8f
#define EPSv 1e-5f

#define TW 16
#define TH 16
#define ICC 8
#define CWS (64*64*9)

// ---------------- scratch ----------------
__device__ float g_x1[Bsz*Cc*NPIX];
__device__ float g_x2[Bsz*Cc*NPIX];
__device__ float g_y1[Bsz*Cc*NPIX];
__device__ float g_y2[Bsz*Cc*NPIX];
__device__ float g_rb[Bsz*Cc*NPIX];
__device__ float g_sb[Bsz*Cc*NPIX];
__device__ float g_xf[Bsz*Cc*NPIX];
__device__ float g_hb[Bsz*Cc*NPIX];
__device__ float g_gv[Bsz*Cc];
__device__ int   g_sel[Bsz*2];
__device__ float g_cofsel[Bsz*2];

// ---------------- 3x3 conv, direct, fp32, 8oc x 8px per thread ----------------
// MODE 0: out = conv+bias
// MODE 1: out = conv+bias+add1+add2
// MODE 2: out = conv+bias+add1
// MODE 3: out = conv+bias+add1 + add2*exp(clamp*(2sig(spre)-1))
// MODE 4: out = lrelu(conv+bias[e])          (expert conv1, indirect)
// MODE 5: out (+)= cof * (conv+bias[e]+add1) (expert conv2, indirect)
template<int MODE>
__global__ __launch_bounds__(256)
void conv3x3_k(const float* __restrict__ in, const float* __restrict__ wts,
               const float* __restrict__ bias, float* __restrict__ out,
               const float* __restrict__ add1, const float* __restrict__ add2,
               const float* __restrict__ spre,
               const int* __restrict__ sel, const float* __restrict__ cofsel,
               int slot, int accum)
{
    __shared__ float s_in[ICC][TH+2][TW+2];
    __shared__ float s_w[ICC][9][64];

    int tid = threadIdx.x;
    int b = blockIdx.z;
    int w0 = blockIdx.x * TW;
    int h0 = blockIdx.y * TH;

    const float* wbase = wts;
    const float* bbase = bias;
    float cw = 1.f;
    if (MODE == 4 || MODE == 5) {
        int e = sel[b*2 + slot];
        wbase = wts + (size_t)e * CWS;
        bbase = bias + e * Cc;
        if (MODE == 5) cw = cofsel[b*2 + slot];
    }

    const float* inb = in + (size_t)b * PLANE;

    int ocg  = tid & 7;
    int ocl0 = ocg * 8;
    int pg   = tid >> 3;       // 0..31
    int ph   = pg >> 1;        // 0..15
    int pw8  = (pg & 1) * 8;   // 0 or 8

    float acc[8][8];
    #pragma unroll
    for (int i = 0; i < 8; i++)
        #pragma unroll
        for (int j = 0; j < 8; j++) acc[i][j] = 0.f;

    for (int ch = 0; ch < Cc; ch += ICC) {
        for (int i = tid; i < ICC*(TH+2)*(TW+2); i += 256) {
            int ic  = i / ((TH+2)*(TW+2));
            int rem = i % ((TH+2)*(TW+2));
            int rr = rem / (TW+2);
            int cc = rem % (TW+2);
            int h = h0 - 1 + rr;
            int w = w0 - 1 + cc;
            float v = 0.f;
            if ((unsigned)h < HWd && (unsigned)w < HWd)
                v = inb[(size_t)(ch+ic)*NPIX + h*HWd + w];
            s_in[ic][rr][cc] = v;
        }
        for (int i = tid; i < ICC*9*64; i += 256) {
            int ocl = i & 63;
            int k   = (i >> 6) % 9;
            int ic  = i / (64*9);
            s_w[ic][k][ocl] = wbase[((size_t)ocl*Cc + (ch+ic))*9 + k];
        }
        __syncthreads();
        #pragma unroll 1
        for (int ic = 0; ic < ICC; ic++) {
            #pragma unroll
            for (int ky = 0; ky < 3; ky++) {
                const float* rp = &s_in[ic][ph+ky][pw8];
                float v[10];
                #pragma unroll
                for (int j = 0; j < 10; j++) v[j] = rp[j];
                #pragma unroll
                for (int tap = 0; tap < 3; tap++) {
                    const float* wp = &s_w[ic][ky*3+tap][ocl0];
                    float4 wa = *(const float4*)wp;
                    float4 wb = *(const float4*)(wp + 4);
                    float w8[8] = {wa.x, wa.y, wa.z, wa.w, wb.x, wb.y, wb.z, wb.w};
                    #pragma unroll
                    for (int i2 = 0; i2 < 8; i2++)
                        #pragma unroll
                        for (int j = 0; j < 8; j++)
                            acc[i2][j] = fmaf(w8[i2], v[tap+j], acc[i2][j]);
                }
            }
        }
        __syncthreads();
    }

    int h = h0 + ph;
    #pragma unroll
    for (int i = 0; i < 8; i++) {
        int oc = ocl0 + i;
        float bv = bbase[oc];
        size_t base = (size_t)b*PLANE + (size_t)oc*NPIX + (size_t)h*HWd + w0 + pw8;
        #pragma unroll
        for (int j = 0; j < 8; j++) {
            size_t idx = base + j;
            float v = acc[i][j] + bv;
            if (MODE == 1) {
                v += add1[idx] + add2[idx];
            } else if (MODE == 2) {
                v += add1[idx];
            } else if (MODE == 3) {
                float sp = spre[idx];
                float sig = 1.f / (1.f + expf(-sp));
                float s = CLAMPv * (2.f*sig - 1.f);
                v += add1[idx] + add2[idx] * expf(s);
            } else if (MODE == 4) {
                v = v > 0.f ? v : LEAKv * v;
            } else if (MODE == 5) {
                v = (v + add1[idx]) * cw;
                if (accum) v += out[idx];
            }
            out[idx] = v;
        }
    }
}

// ---------------- 1x1 GEMM, 8oc x 8px per thread ----------------
template<int IC>
__global__ __launch_bounds__(256)
void gemm1x1_k(const float* __restrict__ inA, const float* __restrict__ inB,
               const float* __restrict__ W, const float* __restrict__ bias,
               float* __restrict__ outA, float* __restrict__ outB)
{
    __shared__ float s_x[16][256];
    __shared__ float s_w[16][64];
    int tid = threadIdx.x;
    int b = blockIdx.z;
    int oc0 = blockIdx.y * 64;
    int p0 = blockIdx.x * 256;
    int ocl0 = (tid & 7) * 8;
    int pp0  = (tid >> 3) * 8;

    float acc[8][8];
    #pragma unroll
    for (int i = 0; i < 8; i++)
        #pragma unroll
        for (int j = 0; j < 8; j++) acc[i][j] = 0.f;

    for (int ch = 0; ch < IC; ch += 16) {
        #pragma unroll
        for (int t = 0; t < 16; t++) {
            int i = tid + t*256;
            int ic = i >> 8, p = i & 255;
            int icg = ch + ic;
            float v;
            if (inB != nullptr) {
                const float* src = (icg < 64) ? inA : inB;
                v = src[(size_t)b*PLANE + (size_t)(icg & 63)*NPIX + p0 + p];
            } else {
                v = inA[((size_t)b*IC + icg)*NPIX + p0 + p];
            }
            s_x[ic][p] = v;
        }
        #pragma unroll
        for (int t = 0; t < 4; t++) {
            int i = tid + t*256;
            int ic = i >> 6, ocl = i & 63;
            s_w[ic][ocl] = W[(size_t)(oc0+ocl)*IC + ch + ic];
        }
        __syncthreads();
        #pragma unroll
        for (int ic = 0; ic < 16; ic++) {
            const float* wp = &s_w[ic][ocl0];
            float4 wa = *(const float4*)wp;
            float4 wb = *(const float4*)(wp + 4);
            float w8[8] = {wa.x, wa.y, wa.z, wa.w, wb.x, wb.y, wb.z, wb.w};
            const float* xp = &s_x[ic][pp0];
            float4 xa = *(const float4*)xp;
            float4 xb = *(const float4*)(xp + 4);
            float xv[8] = {xa.x, xa.y, xa.z, xa.w, xb.x, xb.y, xb.z, xb.w};
            #pragma unroll
            for (int i = 0; i < 8; i++)
                #pragma unroll
                for (int j = 0; j < 8; j++)
                    acc[i][j] = fmaf(w8[i], xv[j], acc[i][j]);
        }
        __syncthreads();
    }

    #pragma unroll
    for (int i = 0; i < 8; i++) {
        int oc = oc0 + ocl0 + i;
        float bv = bias ? bias[oc] : 0.f;
        float* dst = outA;
        int ocd = oc;
        if (outB != nullptr && oc >= 64) { dst = outB; ocd = oc - 64; }
        size_t base = (size_t)b*PLANE + (size_t)ocd*NPIX + p0 + pp0;
        #pragma unroll
        for (int j = 0; j < 8; j++)
            dst[base + j] = acc[i][j] + bv;
    }
}

// ---------------- instance norm (in-place, first 32 channels) ----------------
__global__ __launch_bounds__(256)
void inorm_k(float* __restrict__ r, const float* __restrict__ nw, const float* __restrict__ nb)
{
    int bidx = blockIdx.x;
    int b = bidx >> 5, c = bidx & 31;
    float* p = r + (size_t)b*PLANE + (size_t)c*NPIX;
    int tid = threadIdx.x;
    float s = 0.f, s2 = 0.f;
    for (int i = tid; i < NPIX; i += 256) { float v = p[i]; s += v; s2 += v*v; }
    __shared__ float sh[256], sh2[256];
    sh[tid] = s; sh2[tid] = s2;
    __syncthreads();
    for (int st = 128; st; st >>= 1) {
        if (tid < st) { sh[tid] += sh[tid+st]; sh2[tid] += sh2[tid+st]; }
        __syncthreads();
    }
    float mean = sh[0] * (1.f/NPIX);
    float var = sh2[0] * (1.f/NPIX) - mean*mean;
    float inv = rsqrtf(var + EPSv);
    float ga = nw[c], be = nb[c];
    for (int i = tid; i < NPIX; i += 256)
        p[i] = (p[i] - mean) * inv * ga + be;
}

// ---------------- global max+mean pool ----------------
__global__ __launch_bounds__(256)
void pool_k(const float* __restrict__ xf, float* __restrict__ g)
{
    int bc = blockIdx.x;
    const float* p = xf + (size_t)bc * NPIX;
    int tid = threadIdx.x;
    float mx = -1e30f, sm = 0.f;
    for (int i = tid; i < NPIX; i += 256) { float v = p[i]; mx = fmaxf(mx, v); sm += v; }
    __shared__ float smx[256], ssm[256];
    smx[tid] = mx; ssm[tid] = sm;
    __syncthreads();
    for (int st = 128; st; st >>= 1) {
        if (tid < st) { smx[tid] = fmaxf(smx[tid], smx[tid+st]); ssm[tid] += ssm[tid+st]; }
        __syncthreads();
    }
    if (tid == 0) g[bc] = smx[0] + ssm[0] * (1.f/NPIX);
}

// ---------------- gating ----------------
__global__ void gate_k(const float* __restrict__ g,
                       const float* __restrict__ gw0, const float* __restrict__ gb0,
                       const float* __restrict__ gw1, const float* __restrict__ gb1,
                       float* __restrict__ cof_out, int* __restrict__ sel,
                       float* __restrict__ cofsel)
{
    int b = threadIdx.x;
    if (b >= Bsz) return;
    float lg[4], noi[4];
    for (int e = 0; e < 4; e++) {
        float a0 = gb0[e], a1 = gb1[e];
        for (int c = 0; c < 64; c++) {
            float gv = g[b*64 + c];
            a0 += gw0[e*64 + c] * gv;
            a1 += gw1[e*64 + c] * gv;
        }
        lg[e] = a1 > 0.f ? a1 : LEAKv * a1;
        noi[e] = fmaxf(a0, 0.f) + log1pf(expf(-fabsf(a0)));
    }
    float m = 0.25f * (noi[0] + noi[1] + noi[2] + noi[3]);
    float var = 0.f;
    for (int e = 0; e < 4; e++) { float d = noi[e] - m; var += d*d; }
    float sd = sqrtf(var / 3.f);
    float sc[4];
    for (int e = 0; e < 4; e++) sc[e] = lg[e] + (noi[e] - m) / sd;
    int i0 = 0;
    for (int e = 1; e < 4; e++) if (sc[e] > sc[i0]) i0 = e;
    int i1 = -1;
    for (int e = 0; e < 4; e++) {
        if (e == i0) continue;
        if (i1 < 0 || sc[e] > sc[i1]) i1 = e;
    }
    float mm = fmaxf(lg[i0], lg[i1]);
    float e0 = expf(lg[i0] - mm), e1 = expf(lg[i1] - mm);
    float c0 = e0 / (e0 + e1), c1 = e1 / (e0 + e1);
    if (cof_out) {
        for (int e = 0; e < 4; e++) cof_out[b*4 + e] = 0.f;
        cof_out[b*4 + i0] = c0;
        cof_out[b*4 + i1] = c1;
    }
    sel[b*2 + 0] = i0; sel[b*2 + 1] = i1;
    cofsel[b*2 + 0] = c0; cofsel[b*2 + 1] = c1;
}

// ---------------- launch ----------------
extern "C" void kernel_launch(void* const* d_in, const int* in_sizes, int n_in,
                              void* d_out, int out_size)
{
    const float* x       = (const float*)d_in[0];
    const float* winv    = (const float*)d_in[1];
    const float* blk_w1  = (const float*)d_in[2];
    const float* blk_b1  = (const float*)d_in[3];
    const float* blk_nw  = (const float*)d_in[4];
    const float* blk_nb  = (const float*)d_in[5];
    const float* blk_w2  = (const float*)d_in[6];
    const float* blk_b2  = (const float*)d_in[7];
    const float* fuse_w  = (const float*)d_in[8];
    const float* fuse_b  = (const float*)d_in[9];
    const float* gw0     = (const float*)d_in[10];
    const float* gb0     = (const float*)d_in[11];
    const float* gw1     = (const float*)d_in[12];
    const float* gb1     = (const float*)d_in[13];
    const float* ew1     = (const float*)d_in[14];
    const float* eb1     = (const float*)d_in[15];
    const float* ew2     = (const float*)d_in[16];
    const float* eb2     = (const float*)d_in[17];
    float* out = (float*)d_out;
    float* cof_out = ((size_t)out_size >= BS + Bsz*4) ? out + BS : nullptr;

    float *x1, *x2, *y1, *y2, *rb, *sb, *xf, *hb, *gv, *cofsel; int* sel;
    void* p;
    cudaGetSymbolAddress(&p, g_x1);  x1 = (float*)p;
    cudaGetSymbolAddress(&p, g_x2);  x2 = (float*)p;
    cudaGetSymbolAddress(&p, g_y1);  y1 = (float*)p;
    cudaGetSymbolAddress(&p, g_y2);  y2 = (float*)p;
    cudaGetSymbolAddress(&p, g_rb);  rb = (float*)p;
    cudaGetSymbolAddress(&p, g_sb);  sb = (float*)p;
    cudaGetSymbolAddress(&p, g_xf);  xf = (float*)p;
    cudaGetSymbolAddress(&p, g_hb);  hb = (float*)p;
    cudaGetSymbolAddress(&p, g_gv);  gv = (float*)p;
    cudaGetSymbolAddress(&p, g_sel); sel = (int*)p;
    cudaGetSymbolAddress(&p, g_cofsel); cofsel = (float*)p;

    dim3 cgrid(HWd/TW, HWd/TH, Bsz);   // 8 x 8 x 8
    dim3 wgrid(NPIX/256, 2, Bsz);      // winv: OC=128 -> 2 oc-blocks of 64
    dim3 fgrid(NPIX/256, 1, Bsz);      // fuse: OC=64 -> 1 oc-block

    // z = winv @ x, split into x1 (oc<64) and x2
    gemm1x1_k<128><<<wgrid, 256>>>(x, nullptr, winv, nullptr, x1, x2);

    // hin0(x2) -> y1 = x1 + x2 + conv2(...)
    conv3x3_k<0><<<cgrid, 256>>>(x2, blk_w1 + 0*CWS, blk_b1 + 0*64, rb,
                                 nullptr, nullptr, nullptr, nullptr, nullptr, 0, 0);
    inorm_k<<<Bsz*32, 256>>>(rb, blk_nw + 0*32, blk_nb + 0*32);
    conv3x3_k<1><<<cgrid, 256>>>(rb, blk_w2 + 0*CWS, blk_b2 + 0*64, y1,
                                 x2, x1, nullptr, nullptr, nullptr, 0, 0);

    // hin2(y1) -> s_pre = y1 + conv2(...)
    conv3x3_k<0><<<cgrid, 256>>>(y1, blk_w1 + 2*CWS, blk_b1 + 2*64, rb,
                                 nullptr, nullptr, nullptr, nullptr, nullptr, 0, 0);
    inorm_k<<<Bsz*32, 256>>>(rb, blk_nw + 2*32, blk_nb + 2*32);
    conv3x3_k<2><<<cgrid, 256>>>(rb, blk_w2 + 2*CWS, blk_b2 + 2*64, sb,
                                 y1, nullptr, nullptr, nullptr, nullptr, 0, 0);

    // hin1(y1) fused with flow: y2 = x2*exp(clamp*(2sig(s_pre)-1)) + y1 + conv2(...)
    conv3x3_k<0><<<cgrid, 256>>>(y1, blk_w1 + 1*CWS, blk_b1 + 1*64, rb,
                                 nullptr, nullptr, nullptr, nullptr, nullptr, 0, 0);
    inorm_k<<<Bsz*32, 256>>>(rb, blk_nw + 1*32, blk_nb + 1*32);
    conv3x3_k<3><<<cgrid, 256>>>(rb, blk_w2 + 1*CWS, blk_b2 + 1*64, y2,
                                 y1, x2, sb, nullptr, nullptr, 0, 0);

    // fuse conv1x1 on concat(y1, y2)
    gemm1x1_k<128><<<fgrid, 256>>>(y1, y2, fuse_w, fuse_b, xf, nullptr);

    // gating
    pool_k<<<Bsz*64, 256>>>(xf, gv);
    gate_k<<<1, 32>>>(gv, gw0, gb0, gw1, gb1, cof_out, sel, cofsel);

    // experts (only K=2 selected per batch)
    for (int slot = 0; slot < 2; slot++) {
        conv3x3_k<4><<<cgrid, 256>>>(xf, ew1, eb1, hb,
                                     nullptr, nullptr, nullptr, sel, cofsel, slot, 0);
        conv3x3_k<5><<<cgrid, 256>>>(hb, ew2, eb2, out,
                                     xf, nullptr, nullptr, sel, cofsel, slot, slot);
    }
}

// round 3
// speedup vs baseline: 1.9961x; 1.9961x over previous
#include <cuda_runtime.h>
#include <math.h>

#define Bsz 8
#define Cc 64
#define HWd 128
#define NPIX (HWd*HWd)
#define PLANE ((size_t)Cc*NPIX)
#define BS ((size_t)Bsz*Cc*NPIX)
#define LEAKv 0.2f
#define CLAMPv 0.8f
#define EPSv 1e-5f
#define CWS (64*64*9)

// conv tile
#define CTW 16
#define CTH 8
#define ICC 16
#define INR 10
#define INC 18
#define INPLANE (INR*INC)          // 180
#define SWP 65                      // padded oc stride

// ---------------- scratch ----------------
__device__ float g_x1[Bsz*Cc*NPIX];
__device__ float g_x2[Bsz*Cc*NPIX];
__device__ float g_y1[Bsz*Cc*NPIX];
__device__ float g_y2[Bsz*Cc*NPIX];
__device__ float g_rb[Bsz*Cc*NPIX];
__device__ float g_sb[Bsz*Cc*NPIX];
__device__ float g_xf[Bsz*Cc*NPIX];
__device__ float g_hb[Bsz*Cc*NPIX];
__device__ float g_gv[Bsz*Cc];
__device__ int   g_sel[Bsz*2];
__device__ float g_cofsel[Bsz*2];

__device__ __forceinline__ unsigned f2tf32(float f) {
    unsigned r;
    asm("cvt.rna.tf32.f32 %0, %1;" : "=r"(r) : "f"(f));
    return r;
}

__device__ __forceinline__ void mma_tf32(float* d, const unsigned* a, const unsigned* b) {
    asm volatile(
        "mma.sync.aligned.m16n8k8.row.col.f32.tf32.tf32.f32 "
        "{%0,%1,%2,%3}, {%4,%5,%6,%7}, {%8,%9}, {%0,%1,%2,%3};"
        : "+f"(d[0]), "+f"(d[1]), "+f"(d[2]), "+f"(d[3])
        : "r"(a[0]), "r"(a[1]), "r"(a[2]), "r"(a[3]), "r"(b[0]), "r"(b[1]));
}

// ---------------- 3x3 conv via TF32 warp MMA ----------------
// Block: 256 thr (8 warps), tile = 8 rows x 16 cols pixels (M=128) x 64 oc (N).
// Warp: warp_m = wid&3 -> 2 image rows (M=32), warp_n = wid>>2 -> 32 oc.
// M-tile of 16 = one image row's 16 cols.
// MODE 0: out = conv+bias
// MODE 1: out = conv+bias+add1+add2
// MODE 2: out = conv+bias+add1
// MODE 3: out = conv+bias+add1 + add2*exp(clamp*(2sig(spre)-1))
// MODE 4: out = lrelu(conv+bias[e])          (expert conv1, indirect)
// MODE 5: out (+)= cof * (conv+bias[e]+add1) (expert conv2, indirect)
template<int MODE>
__global__ __launch_bounds__(256)
void conv3x3_mma(const float* __restrict__ in, const float* __restrict__ wts,
                 const float* __restrict__ bias, float* __restrict__ out,
                 const float* __restrict__ add1, const float* __restrict__ add2,
                 const float* __restrict__ spre,
                 const int* __restrict__ sel, const float* __restrict__ cofsel,
                 int slot, int accum)
{
    __shared__ unsigned s_in[ICC * INPLANE];      // [ic][10][18]
    __shared__ unsigned s_w[9 * ICC * SWP];       // [tap][ic][65]

    int tid = threadIdx.x;
    int wid = tid >> 5;
    int lane = tid & 31;
    int l4 = lane & 3;
    int g  = lane >> 2;
    int warp_m = wid & 3;
    int warp_n = wid >> 2;
    int wm2 = warp_m * 2;
    int n0 = warp_n * 32;

    int b  = blockIdx.z;
    int w0 = blockIdx.x * CTW;
    int h0 = blockIdx.y * CTH;

    const float* wbase = wts;
    const float* bbase = bias;
    float cw = 1.f;
    if (MODE == 4 || MODE == 5) {
        int e = sel[b*2 + slot];
        wbase = wts + (size_t)e * CWS;
        bbase = bias + e * Cc;
        if (MODE == 5) cw = cofsel[b*2 + slot];
    }
    const float* inb = in + (size_t)b * PLANE;

    float d[2][4][4];
    #pragma unroll
    for (int mt = 0; mt < 2; mt++)
        #pragma unroll
        for (int nt = 0; nt < 4; nt++)
            #pragma unroll
            for (int r = 0; r < 4; r++) d[mt][nt][r] = 0.f;

    for (int ch = 0; ch < Cc; ch += ICC) {
        // load input tile (with halo) as tf32
        for (int i = tid; i < ICC*INPLANE; i += 256) {
            int ic  = i / INPLANE;
            int rem = i % INPLANE;
            int rr = rem / INC;
            int cc = rem % INC;
            int h = h0 - 1 + rr;
            int w = w0 - 1 + cc;
            float v = 0.f;
            if ((unsigned)h < HWd && (unsigned)w < HWd)
                v = inb[(size_t)(ch+ic)*NPIX + h*HWd + w];
            s_in[i] = f2tf32(v);
        }
        // load weights [tap][ic][oc] as tf32 (gmem OIHW)
        for (int i = tid; i < 9*ICC*64; i += 256) {
            int tap = i % 9;
            int ic  = (i / 9) % ICC;
            int oc  = i / (9*ICC);
            s_w[(tap*ICC + ic)*SWP + oc] = f2tf32(wbase[((size_t)oc*Cc + ch + ic)*9 + tap]);
        }
        __syncthreads();

        #pragma unroll
        for (int tap = 0; tap < 9; tap++) {
            int ky = tap / 3, kx = tap % 3;
            #pragma unroll
            for (int ks = 0; ks < 2; ks++) {
                int ab = (ks*8 + l4)*INPLANE + (wm2 + ky)*INC + kx + g;
                unsigned a[2][4];
                #pragma unroll
                for (int mt = 0; mt < 2; mt++) {
                    int o = ab + mt*INC;
                    a[mt][0] = s_in[o];
                    a[mt][1] = s_in[o + 8];
                    a[mt][2] = s_in[o + 4*INPLANE];
                    a[mt][3] = s_in[o + 4*INPLANE + 8];
                }
                int bb = (tap*ICC + ks*8 + l4)*SWP + n0 + g;
                unsigned bq[4][2];
                #pragma unroll
                for (int nt = 0; nt < 4; nt++) {
                    bq[nt][0] = s_w[bb + nt*8];
                    bq[nt][1] = s_w[bb + 4*SWP + nt*8];
                }
                #pragma unroll
                for (int mt = 0; mt < 2; mt++)
                    #pragma unroll
                    for (int nt = 0; nt < 4; nt++)
                        mma_tf32(d[mt][nt], a[mt], bq[nt]);
            }
        }
        __syncthreads();
    }

    // epilogue
    #pragma unroll
    for (int mt = 0; mt < 2; mt++) {
        int h = h0 + wm2 + mt;
        #pragma unroll
        for (int nt = 0; nt < 4; nt++) {
            int oc = n0 + nt*8 + l4*2;
            float bv0 = bbase[oc], bv1 = bbase[oc+1];
            size_t p0 = (size_t)b*PLANE + (size_t)oc*NPIX + (size_t)h*HWd;
            size_t p1 = p0 + NPIX;
            int wa = w0 + g, wb2 = wa + 8;
            float vv[4] = { d[mt][nt][0] + bv0, d[mt][nt][1] + bv1,
                            d[mt][nt][2] + bv0, d[mt][nt][3] + bv1 };
            size_t ix[4] = { p0 + wa, p1 + wa, p0 + wb2, p1 + wb2 };
            #pragma unroll
            for (int r = 0; r < 4; r++) {
                size_t idx = ix[r];
                float v = vv[r];
                if (MODE == 1) {
                    v += add1[idx] + add2[idx];
                } else if (MODE == 2) {
                    v += add1[idx];
                } else if (MODE == 3) {
                    float sp = spre[idx];
                    float sig = 1.f / (1.f + expf(-sp));
                    float s = CLAMPv * (2.f*sig - 1.f);
                    v += add1[idx] + add2[idx] * expf(s);
                } else if (MODE == 4) {
                    v = v > 0.f ? v : LEAKv * v;
                } else if (MODE == 5) {
                    v = (v + add1[idx]) * cw;
                    if (accum) v += out[idx];
                }
                out[idx] = v;
            }
        }
    }
}

// ---------------- 1x1 GEMM (fp32 scalar, unchanged from R1 shape) ----------------
#define FMA_OC4(wv, a0, a1, a2, a3) \
    acc[0][0] += wv.x * a0; acc[0][1] += wv.x * a1; acc[0][2] += wv.x * a2; acc[0][3] += wv.x * a3; \
    acc[1][0] += wv.y * a0; acc[1][1] += wv.y * a1; acc[1][2] += wv.y * a2; acc[1][3] += wv.y * a3; \
    acc[2][0] += wv.z * a0; acc[2][1] += wv.z * a1; acc[2][2] += wv.z * a2; acc[2][3] += wv.z * a3; \
    acc[3][0] += wv.w * a0; acc[3][1] += wv.w * a1; acc[3][2] += wv.w * a2; acc[3][3] += wv.w * a3;

template<int IC>
__global__ __launch_bounds__(256)
void gemm1x1_k(const float* __restrict__ inA, const float* __restrict__ inB,
               const float* __restrict__ W, const float* __restrict__ bias,
               float* __restrict__ outA, float* __restrict__ outB)
{
    __shared__ float s_x[16][128];
    __shared__ float s_w[16][32];
    int tid = threadIdx.x;
    int b = blockIdx.z;
    int oc0 = blockIdx.y * 32;
    int p0 = blockIdx.x * 128;
    int ocl0 = (tid & 7) * 4;
    int pp0 = (tid >> 3) * 4;

    float acc[4][4];
    #pragma unroll
    for (int i = 0; i < 4; i++)
        #pragma unroll
        for (int j = 0; j < 4; j++) acc[i][j] = 0.f;

    for (int ch = 0; ch < IC; ch += 16) {
        #pragma unroll
        for (int t = 0; t < 8; t++) {
            int i = tid + t*256;
            int ic = i >> 7, p = i & 127;
            int icg = ch + ic;
            float v;
            if (inB != nullptr) {
                const float* src = (icg < 64) ? inA : inB;
                v = src[(size_t)b*PLANE + (size_t)(icg & 63)*NPIX + p0 + p];
            } else {
                v = inA[((size_t)b*IC + icg)*NPIX + p0 + p];
            }
            s_x[ic][p] = v;
        }
        #pragma unroll
        for (int t = 0; t < 2; t++) {
            int i = tid + t*256;
            int ic = i >> 5, ocl = i & 31;
            s_w[ic][ocl] = W[(size_t)(oc0+ocl)*IC + ch + ic];
        }
        __syncthreads();
        #pragma unroll
        for (int ic = 0; ic < 16; ic++) {
            float4 wv = *(const float4*)&s_w[ic][ocl0];
            float x0 = s_x[ic][pp0+0], x1 = s_x[ic][pp0+1];
            float x2 = s_x[ic][pp0+2], x3 = s_x[ic][pp0+3];
            FMA_OC4(wv, x0, x1, x2, x3);
        }
        __syncthreads();
    }

    #pragma unroll
    for (int i = 0; i < 4; i++) {
        int oc = oc0 + ocl0 + i;
        float bv = bias ? bias[oc] : 0.f;
        float* dst = outA;
        int ocd = oc;
        if (outB != nullptr && oc >= 64) { dst = outB; ocd = oc - 64; }
        size_t base = (size_t)b*PLANE + (size_t)ocd*NPIX + p0 + pp0;
        #pragma unroll
        for (int j = 0; j < 4; j++)
            dst[base + j] = acc[i][j] + bv;
    }
}

// ---------------- instance norm ----------------
__global__ __launch_bounds__(256)
void inorm_k(float* __restrict__ r, const float* __restrict__ nw, const float* __restrict__ nb)
{
    int bidx = blockIdx.x;
    int b = bidx >> 5, c = bidx & 31;
    float* p = r + (size_t)b*PLANE + (size_t)c*NPIX;
    int tid = threadIdx.x;
    float s = 0.f, s2 = 0.f;
    for (int i = tid; i < NPIX; i += 256) { float v = p[i]; s += v; s2 += v*v; }
    __shared__ float sh[256], sh2[256];
    sh[tid] = s; sh2[tid] = s2;
    __syncthreads();
    for (int st = 128; st; st >>= 1) {
        if (tid < st) { sh[tid] += sh[tid+st]; sh2[tid] += sh2[tid+st]; }
        __syncthreads();
    }
    float mean = sh[0] * (1.f/NPIX);
    float var = sh2[0] * (1.f/NPIX) - mean*mean;
    float inv = rsqrtf(var + EPSv);
    float ga = nw[c], be = nb[c];
    for (int i = tid; i < NPIX; i += 256)
        p[i] = (p[i] - mean) * inv * ga + be;
}

// ---------------- pool ----------------
__global__ __launch_bounds__(256)
void pool_k(const float* __restrict__ xf, float* __restrict__ g)
{
    int bc = blockIdx.x;
    const float* p = xf + (size_t)bc * NPIX;
    int tid = threadIdx.x;
    float mx = -1e30f, sm = 0.f;
    for (int i = tid; i < NPIX; i += 256) { float v = p[i]; mx = fmaxf(mx, v); sm += v; }
    __shared__ float smx[256], ssm[256];
    smx[tid] = mx; ssm[tid] = sm;
    __syncthreads();
    for (int st = 128; st; st >>= 1) {
        if (tid < st) { smx[tid] = fmaxf(smx[tid], smx[tid+st]); ssm[tid] += ssm[tid+st]; }
        __syncthreads();
    }
    if (tid == 0) g[bc] = smx[0] + ssm[0] * (1.f/NPIX);
}

// ---------------- gating ----------------
__global__ void gate_k(const float* __restrict__ g,
                       const float* __restrict__ gw0, const float* __restrict__ gb0,
                       const float* __restrict__ gw1, const float* __restrict__ gb1,
                       float* __restrict__ cof_out, int* __restrict__ sel,
                       float* __restrict__ cofsel)
{
    int b = threadIdx.x;
    if (b >= Bsz) return;
    float lg[4], noi[4];
    for (int e = 0; e < 4; e++) {
        float a0 = gb0[e], a1 = gb1[e];
        for (int c = 0; c < 64; c++) {
            float gv = g[b*64 + c];
            a0 += gw0[e*64 + c] * gv;
            a1 += gw1[e*64 + c] * gv;
        }
        lg[e] = a1 > 0.f ? a1 : LEAKv * a1;
        noi[e] = fmaxf(a0, 0.f) + log1pf(expf(-fabsf(a0)));
    }
    float m = 0.25f * (noi[0] + noi[1] + noi[2] + noi[3]);
    float var = 0.f;
    for (int e = 0; e < 4; e++) { float dd = noi[e] - m; var += dd*dd; }
    float sd = sqrtf(var / 3.f);
    float sc[4];
    for (int e = 0; e < 4; e++) sc[e] = lg[e] + (noi[e] - m) / sd;
    int i0 = 0;
    for (int e = 1; e < 4; e++) if (sc[e] > sc[i0]) i0 = e;
    int i1 = -1;
    for (int e = 0; e < 4; e++) {
        if (e == i0) continue;
        if (i1 < 0 || sc[e] > sc[i1]) i1 = e;
    }
    float mm = fmaxf(lg[i0], lg[i1]);
    float e0 = expf(lg[i0] - mm), e1 = expf(lg[i1] - mm);
    float c0 = e0 / (e0 + e1), c1 = e1 / (e0 + e1);
    if (cof_out) {
        for (int e = 0; e < 4; e++) cof_out[b*4 + e] = 0.f;
        cof_out[b*4 + i0] = c0;
        cof_out[b*4 + i1] = c1;
    }
    sel[b*2 + 0] = i0; sel[b*2 + 1] = i1;
    cofsel[b*2 + 0] = c0; cofsel[b*2 + 1] = c1;
}

// ---------------- launch ----------------
extern "C" void kernel_launch(void* const* d_in, const int* in_sizes, int n_in,
                              void* d_out, int out_size)
{
    const float* x       = (const float*)d_in[0];
    const float* winv    = (const float*)d_in[1];
    const float* blk_w1  = (const float*)d_in[2];
    const float* blk_b1  = (const float*)d_in[3];
    const float* blk_nw  = (const float*)d_in[4];
    const float* blk_nb  = (const float*)d_in[5];
    const float* blk_w2  = (const float*)d_in[6];
    const float* blk_b2  = (const float*)d_in[7];
    const float* fuse_w  = (const float*)d_in[8];
    const float* fuse_b  = (const float*)d_in[9];
    const float* gw0     = (const float*)d_in[10];
    const float* gb0     = (const float*)d_in[11];
    const float* gw1     = (const float*)d_in[12];
    const float* gb1     = (const float*)d_in[13];
    const float* ew1     = (const float*)d_in[14];
    const float* eb1     = (const float*)d_in[15];
    const float* ew2     = (const float*)d_in[16];
    const float* eb2     = (const float*)d_in[17];
    float* out = (float*)d_out;
    float* cof_out = ((size_t)out_size >= BS + Bsz*4) ? out + BS : nullptr;

    float *x1, *x2, *y1, *y2, *rb, *sb, *xf, *hb, *gv, *cofsel; int* sel;
    void* p;
    cudaGetSymbolAddress(&p, g_x1);  x1 = (float*)p;
    cudaGetSymbolAddress(&p, g_x2);  x2 = (float*)p;
    cudaGetSymbolAddress(&p, g_y1);  y1 = (float*)p;
    cudaGetSymbolAddress(&p, g_y2);  y2 = (float*)p;
    cudaGetSymbolAddress(&p, g_rb);  rb = (float*)p;
    cudaGetSymbolAddress(&p, g_sb);  sb = (float*)p;
    cudaGetSymbolAddress(&p, g_xf);  xf = (float*)p;
    cudaGetSymbolAddress(&p, g_hb);  hb = (float*)p;
    cudaGetSymbolAddress(&p, g_gv);  gv = (float*)p;
    cudaGetSymbolAddress(&p, g_sel); sel = (int*)p;
    cudaGetSymbolAddress(&p, g_cofsel); cofsel = (float*)p;

    dim3 cgrid(HWd/CTW, HWd/CTH, Bsz);   // 8 x 16 x 8
    dim3 wgrid(NPIX/128, 4, Bsz);
    dim3 fgrid(NPIX/128, 2, Bsz);

    // z = winv @ x -> x1, x2
    gemm1x1_k<128><<<wgrid, 256>>>(x, nullptr, winv, nullptr, x1, x2);

    // hin0(x2) -> y1
    conv3x3_mma<0><<<cgrid, 256>>>(x2, blk_w1 + 0*CWS, blk_b1 + 0*64, rb,
                                   nullptr, nullptr, nullptr, nullptr, nullptr, 0, 0);
    inorm_k<<<Bsz*32, 256>>>(rb, blk_nw + 0*32, blk_nb + 0*32);
    conv3x3_mma<1><<<cgrid, 256>>>(rb, blk_w2 + 0*CWS, blk_b2 + 0*64, y1,
                                   x2, x1, nullptr, nullptr, nullptr, 0, 0);

    // hin2(y1) -> s_pre
    conv3x3_mma<0><<<cgrid, 256>>>(y1, blk_w1 + 2*CWS, blk_b1 + 2*64, rb,
                                   nullptr, nullptr, nullptr, nullptr, nullptr, 0, 0);
    inorm_k<<<Bsz*32, 256>>>(rb, blk_nw + 2*32, blk_nb + 2*32);
    conv3x3_mma<2><<<cgrid, 256>>>(rb, blk_w2 + 2*CWS, blk_b2 + 2*64, sb,
                                   y1, nullptr, nullptr, nullptr, nullptr, 0, 0);

    // hin1(y1) fused with flow -> y2
    conv3x3_mma<0><<<cgrid, 256>>>(y1, blk_w1 + 1*CWS, blk_b1 + 1*64, rb,
                                   nullptr, nullptr, nullptr, nullptr, nullptr, 0, 0);
    inorm_k<<<Bsz*32, 256>>>(rb, blk_nw + 1*32, blk_nb + 1*32);
    conv3x3_mma<3><<<cgrid, 256>>>(rb, blk_w2 + 1*CWS, blk_b2 + 1*64, y2,
                                   y1, x2, sb, nullptr, nullptr, 0, 0);

    // fuse 1x1 on concat(y1, y2)
    gemm1x1_k<128><<<fgrid, 256>>>(y1, y2, fuse_w, fuse_b, xf, nullptr);

    // gating
    pool_k<<<Bsz*64, 256>>>(xf, gv);
    gate_k<<<1, 32>>>(gv, gw0, gb0, gw1, gb1, cof_out, sel, cofsel);

    // experts (K=2 selected per batch)
    for (int slot = 0; slot < 2; slot++) {
        conv3x3_mma<4><<<cgrid, 256>>>(xf, ew1, eb1, hb,
                                       nullptr, nullptr, nullptr, sel, cofsel, slot, 0);
        conv3x3_mma<5><<<cgrid, 256>>>(hb, ew2, eb2, out,
                                       xf, nullptr, nullptr, sel, cofsel, slot, slot);
    }
}

// round 4
// speedup vs baseline: 2.8570x; 1.4313x over previous
#include <cuda_runtime.h>
#include <math.h>

#define Bsz 8
#define Cc 64
#define HWd 128
#define NPIX (HWd*HWd)
#define PLANE ((size_t)Cc*NPIX)
#define BS ((size_t)Bsz*Cc*NPIX)
#define LEAKv 0.2f
#define CLAMPv 0.8f
#define EPSv 1e-5f
#define CWS (64*64*9)

// conv tile: block = 128 px (8 rows x 16 cols) x 64 oc, 8 warps (4 in M, 2 in N)
#define CTW 16
#define CTH 8
#define INC 18
#define INREAL (10*INC)       // 180
#define INPAD 196             // uint2 row stride: 196 % 16 == 4 -> conflict-free l4 spacing
#define WPAD 68               // 68 % 16 == 4

// ---------------- scratch ----------------
__device__ float g_x1[Bsz*Cc*NPIX];
__device__ float g_x2[Bsz*Cc*NPIX];
__device__ float g_y1[Bsz*Cc*NPIX];
__device__ float g_y2[Bsz*Cc*NPIX];
__device__ float g_rb[Bsz*Cc*NPIX];
__device__ float g_sb[Bsz*Cc*NPIX];
__device__ float g_xf[Bsz*Cc*NPIX];
__device__ float g_hb[Bsz*Cc*NPIX];
__device__ float g_gv[Bsz*Cc];
__device__ int   g_sel[Bsz*2];
__device__ float g_cofsel[Bsz*2];

__device__ __forceinline__ unsigned f2tf32(float f) {
    unsigned r;
    asm("cvt.rna.tf32.f32 %0, %1;" : "=r"(r) : "f"(f));
    return r;
}

__device__ __forceinline__ void mma_tf32(float* d, const unsigned* a, const unsigned* b) {
    asm volatile(
        "mma.sync.aligned.m16n8k8.row.col.f32.tf32.tf32.f32 "
        "{%0,%1,%2,%3}, {%4,%5,%6,%7}, {%8,%9}, {%0,%1,%2,%3};"
        : "+f"(d[0]), "+f"(d[1]), "+f"(d[2]), "+f"(d[3])
        : "r"(a[0]), "r"(a[1]), "r"(a[2]), "r"(a[3]), "r"(b[0]), "r"(b[1]));
}

// ---------------- 3x3 conv via TF32 MMA, uint2 (k,k+4)-paired smem ----------------
// MODE 0: out = conv+bias
// MODE 1: out = conv+bias+add1+add2
// MODE 2: out = conv+bias+add1
// MODE 3: out = conv+bias+add1 + add2*exp(clamp*(2sig(spre)-1))
// MODE 4: out = lrelu(conv+bias[e])          (expert conv1, indirect)
// MODE 5: out (+)= cof * (conv+bias[e]+add1) (expert conv2, indirect)
template<int MODE>
__global__ __launch_bounds__(256)
void conv3x3_mma(const float* __restrict__ in, const float* __restrict__ wts,
                 const float* __restrict__ bias, float* __restrict__ out,
                 const float* __restrict__ add1, const float* __restrict__ add2,
                 const float* __restrict__ spre,
                 const int* __restrict__ sel, const float* __restrict__ cofsel,
                 int slot, int accum)
{
    __shared__ uint2 s_in[4 * INPAD];     // [kq][10x18 px] -> pair (ic=ch+kq, ch+kq+4)
    __shared__ uint2 s_w[36 * WPAD];      // [tap*4+kq][oc] -> pair (ic, ic+4)

    int tid = threadIdx.x;
    int wid = tid >> 5;
    int lane = tid & 31;
    int l4 = lane & 3;
    int g  = lane >> 2;
    int warp_m = wid & 3;
    int warp_n = wid >> 2;
    int wm2 = warp_m * 2;
    int n0 = warp_n * 32;

    int b  = blockIdx.z;
    int w0 = blockIdx.x * CTW;
    int h0 = blockIdx.y * CTH;

    const float* wbase = wts;
    const float* bbase = bias;
    float cw = 1.f;
    if (MODE == 4 || MODE == 5) {
        int e = sel[b*2 + slot];
        wbase = wts + (size_t)e * CWS;
        bbase = bias + e * Cc;
        if (MODE == 5) cw = cofsel[b*2 + slot];
    }
    const float* inb = in + (size_t)b * PLANE;

    float d[2][4][4];
    #pragma unroll
    for (int mt = 0; mt < 2; mt++)
        #pragma unroll
        for (int nt = 0; nt < 4; nt++)
            #pragma unroll
            for (int r = 0; r < 4; r++) d[mt][nt][r] = 0.f;

    for (int ch = 0; ch < Cc; ch += 8) {
        // input tile with halo: pairs (ch+kq, ch+kq+4)
        for (int i = tid; i < 4*INREAL; i += 256) {
            int kq  = i / INREAL;
            int rem = i % INREAL;
            int rr = rem / INC;
            int cc = rem % INC;
            int h = h0 - 1 + rr;
            int w = w0 - 1 + cc;
            unsigned v0 = 0, v1 = 0;
            if ((unsigned)h < HWd && (unsigned)w < HWd) {
                size_t o = (size_t)(ch+kq)*NPIX + h*HWd + w;
                v0 = f2tf32(inb[o]);
                v1 = f2tf32(inb[o + 4*NPIX]);
            }
            s_in[kq*INPAD + rem] = make_uint2(v0, v1);
        }
        // weights: row = tap*4+kq, col = oc
        for (int i = tid; i < 36*64; i += 256) {
            int q  = i % 36;
            int oc = i / 36;
            int kq = q & 3;
            int tap = q >> 2;
            size_t o = ((size_t)oc*Cc + ch + kq)*9 + tap;
            s_w[q*WPAD + oc] = make_uint2(f2tf32(wbase[o]), f2tf32(wbase[o + 4*9]));
        }
        __syncthreads();

        #pragma unroll
        for (int tap = 0; tap < 9; tap++) {
            int ky = tap / 3, kx = tap % 3;
            int abase = l4*INPAD + (wm2 + ky)*INC + kx + g;
            unsigned a[2][4];
            #pragma unroll
            for (int mt = 0; mt < 2; mt++) {
                uint2 p0 = s_in[abase + mt*INC];
                uint2 p1 = s_in[abase + mt*INC + 8];
                a[mt][0] = p0.x; a[mt][1] = p1.x; a[mt][2] = p0.y; a[mt][3] = p1.y;
            }
            int bb = (tap*4 + l4)*WPAD + n0 + g;
            unsigned bq[4][2];
            #pragma unroll
            for (int nt = 0; nt < 4; nt++) {
                uint2 q = s_w[bb + nt*8];
                bq[nt][0] = q.x; bq[nt][1] = q.y;
            }
            #pragma unroll
            for (int mt = 0; mt < 2; mt++)
                #pragma unroll
                for (int nt = 0; nt < 4; nt++)
                    mma_tf32(d[mt][nt], a[mt], bq[nt]);
        }
        __syncthreads();
    }

    // epilogue
    #pragma unroll
    for (int mt = 0; mt < 2; mt++) {
        int h = h0 + wm2 + mt;
        #pragma unroll
        for (int nt = 0; nt < 4; nt++) {
            int oc = n0 + nt*8 + l4*2;
            float bv0 = bbase[oc], bv1 = bbase[oc+1];
            size_t p0 = (size_t)b*PLANE + (size_t)oc*NPIX + (size_t)h*HWd;
            size_t p1 = p0 + NPIX;
            int wa = w0 + g, wb2 = wa + 8;
            float vv[4] = { d[mt][nt][0] + bv0, d[mt][nt][1] + bv1,
                            d[mt][nt][2] + bv0, d[mt][nt][3] + bv1 };
            size_t ix[4] = { p0 + wa, p1 + wa, p0 + wb2, p1 + wb2 };
            #pragma unroll
            for (int r = 0; r < 4; r++) {
                size_t idx = ix[r];
                float v = vv[r];
                if (MODE == 1) {
                    v += add1[idx] + add2[idx];
                } else if (MODE == 2) {
                    v += add1[idx];
                } else if (MODE == 3) {
                    float sp = spre[idx];
                    float sig = 1.f / (1.f + expf(-sp));
                    float s = CLAMPv * (2.f*sig - 1.f);
                    v += add1[idx] + add2[idx] * expf(s);
                } else if (MODE == 4) {
                    v = v > 0.f ? v : LEAKv * v;
                } else if (MODE == 5) {
                    v = (v + add1[idx]) * cw;
                    if (accum) v += out[idx];
                }
                out[idx] = v;
            }
        }
    }
}

// ---------------- 1x1 GEMM via TF32 MMA ----------------
// Block: M=128 contiguous pixels, N=64 (blockIdx.y picks oc block), K=IC.
// Same warp layout as conv: 4 warps in M, 2 in N.
#define GPAD 132   // 132 % 16 == 4

template<int IC>
__global__ __launch_bounds__(256)
void gemm1x1_mma(const float* __restrict__ inA, const float* __restrict__ inB,
                 const float* __restrict__ W, const float* __restrict__ bias,
                 float* __restrict__ outA, float* __restrict__ outB)
{
    __shared__ uint2 s_x[8 * GPAD];   // [ks*4+kq][128 px]
    __shared__ uint2 s_w[8 * WPAD];   // [ks*4+kq][oc]

    int tid = threadIdx.x;
    int wid = tid >> 5;
    int lane = tid & 31;
    int l4 = lane & 3;
    int g  = lane >> 2;
    int warp_m = wid & 3;
    int warp_n = wid >> 2;
    int n0 = warp_n * 32;

    int b   = blockIdx.z;
    int oc0 = blockIdx.y * 64;
    int p0  = blockIdx.x * 128;

    float d[2][4][4];
    #pragma unroll
    for (int mt = 0; mt < 2; mt++)
        #pragma unroll
        for (int nt = 0; nt < 4; nt++)
            #pragma unroll
            for (int r = 0; r < 4; r++) d[mt][nt][r] = 0.f;

    for (int ch = 0; ch < IC; ch += 16) {
        // activations
        for (int i = tid; i < 8*128; i += 256) {
            int q = i >> 7;         // ks*4+kq
            int p = i & 127;
            int ic0 = ch + (q >> 2)*8 + (q & 3);
            unsigned v0, v1;
            if (inB != nullptr) {
                const float* s0 = (ic0 < 64) ? inA : inB;
                const float* s1 = (ic0+4 < 64) ? inA : inB;
                v0 = f2tf32(s0[(size_t)b*PLANE + (size_t)(ic0 & 63)*NPIX + p0 + p]);
                v1 = f2tf32(s1[(size_t)b*PLANE + (size_t)((ic0+4) & 63)*NPIX + p0 + p]);
            } else {
                v0 = f2tf32(inA[((size_t)b*IC + ic0)*NPIX + p0 + p]);
                v1 = f2tf32(inA[((size_t)b*IC + ic0 + 4)*NPIX + p0 + p]);
            }
            s_x[q*GPAD + p] = make_uint2(v0, v1);
        }
        // weights [oc][ic] row-major
        for (int i = tid; i < 8*64; i += 256) {
            int q  = i & 7;
            int oc = i >> 3;
            int ic0 = ch + (q >> 2)*8 + (q & 3);
            size_t o = (size_t)(oc0 + oc)*IC + ic0;
            s_w[q*WPAD + oc] = make_uint2(f2tf32(W[o]), f2tf32(W[o + 4]));
        }
        __syncthreads();

        #pragma unroll
        for (int ks = 0; ks < 2; ks++) {
            int abase = (ks*4 + l4)*GPAD + warp_m*32 + g;
            unsigned a[2][4];
            #pragma unroll
            for (int mt = 0; mt < 2; mt++) {
                uint2 q0 = s_x[abase + mt*16];
                uint2 q1 = s_x[abase + mt*16 + 8];
                a[mt][0] = q0.x; a[mt][1] = q1.x; a[mt][2] = q0.y; a[mt][3] = q1.y;
            }
            int bb = (ks*4 + l4)*WPAD + n0 + g;
            unsigned bq[4][2];
            #pragma unroll
            for (int nt = 0; nt < 4; nt++) {
                uint2 q = s_w[bb + nt*8];
                bq[nt][0] = q.x; bq[nt][1] = q.y;
            }
            #pragma unroll
            for (int mt = 0; mt < 2; mt++)
                #pragma unroll
                for (int nt = 0; nt < 4; nt++)
                    mma_tf32(d[mt][nt], a[mt], bq[nt]);
        }
        __syncthreads();
    }

    #pragma unroll
    for (int mt = 0; mt < 2; mt++) {
        #pragma unroll
        for (int nt = 0; nt < 4; nt++) {
            int oc = oc0 + n0 + nt*8 + l4*2;
            float bv0 = bias ? bias[oc] : 0.f;
            float bv1 = bias ? bias[oc+1] : 0.f;
            float* dst = outA;
            int ocd = oc;
            if (outB != nullptr && oc >= 64) { dst = outB; ocd = oc - 64; }
            int pix = p0 + warp_m*32 + mt*16 + g;
            size_t q0 = (size_t)b*PLANE + (size_t)ocd*NPIX + pix;
            size_t q1 = q0 + NPIX;
            dst[q0]     = d[mt][nt][0] + bv0;
            dst[q1]     = d[mt][nt][1] + bv1;
            dst[q0 + 8] = d[mt][nt][2] + bv0;
            dst[q1 + 8] = d[mt][nt][3] + bv1;
        }
    }
}

// ---------------- instance norm ----------------
__global__ __launch_bounds__(256)
void inorm_k(float* __restrict__ r, const float* __restrict__ nw, const float* __restrict__ nb)
{
    int bidx = blockIdx.x;
    int b = bidx >> 5, c = bidx & 31;
    float* p = r + (size_t)b*PLANE + (size_t)c*NPIX;
    int tid = threadIdx.x;
    float s = 0.f, s2 = 0.f;
    for (int i = tid; i < NPIX; i += 256) { float v = p[i]; s += v; s2 += v*v; }
    __shared__ float sh[256], sh2[256];
    sh[tid] = s; sh2[tid] = s2;
    __syncthreads();
    for (int st = 128; st; st >>= 1) {
        if (tid < st) { sh[tid] += sh[tid+st]; sh2[tid] += sh2[tid+st]; }
        __syncthreads();
    }
    float mean = sh[0] * (1.f/NPIX);
    float var = sh2[0] * (1.f/NPIX) - mean*mean;
    float inv = rsqrtf(var + EPSv);
    float ga = nw[c], be = nb[c];
    for (int i = tid; i < NPIX; i += 256)
        p[i] = (p[i] - mean) * inv * ga + be;
}

// ---------------- pool ----------------
__global__ __launch_bounds__(256)
void pool_k(const float* __restrict__ xf, float* __restrict__ g)
{
    int bc = blockIdx.x;
    const float* p = xf + (size_t)bc * NPIX;
    int tid = threadIdx.x;
    float mx = -1e30f, sm = 0.f;
    for (int i = tid; i < NPIX; i += 256) { float v = p[i]; mx = fmaxf(mx, v); sm += v; }
    __shared__ float smx[256], ssm[256];
    smx[tid] = mx; ssm[tid] = sm;
    __syncthreads();
    for (int st = 128; st; st >>= 1) {
        if (tid < st) { smx[tid] = fmaxf(smx[tid], smx[tid+st]); ssm[tid] += ssm[tid+st]; }
        __syncthreads();
    }
    if (tid == 0) g[bc] = smx[0] + ssm[0] * (1.f/NPIX);
}

// ---------------- gating ----------------
__global__ void gate_k(const float* __restrict__ g,
                       const float* __restrict__ gw0, const float* __restrict__ gb0,
                       const float* __restrict__ gw1, const float* __restrict__ gb1,
                       float* __restrict__ cof_out, int* __restrict__ sel,
                       float* __restrict__ cofsel)
{
    int b = threadIdx.x;
    if (b >= Bsz) return;
    float lg[4], noi[4];
    for (int e = 0; e < 4; e++) {
        float a0 = gb0[e], a1 = gb1[e];
        for (int c = 0; c < 64; c++) {
            float gv = g[b*64 + c];
            a0 += gw0[e*64 + c] * gv;
            a1 += gw1[e*64 + c] * gv;
        }
        lg[e] = a1 > 0.f ? a1 : LEAKv * a1;
        noi[e] = fmaxf(a0, 0.f) + log1pf(expf(-fabsf(a0)));
    }
    float m = 0.25f * (noi[0] + noi[1] + noi[2] + noi[3]);
    float var = 0.f;
    for (int e = 0; e < 4; e++) { float dd = noi[e] - m; var += dd*dd; }
    float sd = sqrtf(var / 3.f);
    float sc[4];
    for (int e = 0; e < 4; e++) sc[e] = lg[e] + (noi[e] - m) / sd;
    int i0 = 0;
    for (int e = 1; e < 4; e++) if (sc[e] > sc[i0]) i0 = e;
    int i1 = -1;
    for (int e = 0; e < 4; e++) {
        if (e == i0) continue;
        if (i1 < 0 || sc[e] > sc[i1]) i1 = e;
    }
    float mm = fmaxf(lg[i0], lg[i1]);
    float e0 = expf(lg[i0] - mm), e1 = expf(lg[i1] - mm);
    float c0 = e0 / (e0 + e1), c1 = e1 / (e0 + e1);
    if (cof_out) {
        for (int e = 0; e < 4; e++) cof_out[b*4 + e] = 0.f;
        cof_out[b*4 + i0] = c0;
        cof_out[b*4 + i1] = c1;
    }
    sel[b*2 + 0] = i0; sel[b*2 + 1] = i1;
    cofsel[b*2 + 0] = c0; cofsel[b*2 + 1] = c1;
}

// ---------------- launch ----------------
extern "C" void kernel_launch(void* const* d_in, const int* in_sizes, int n_in,
                              void* d_out, int out_size)
{
    const float* x       = (const float*)d_in[0];
    const float* winv    = (const float*)d_in[1];
    const float* blk_w1  = (const float*)d_in[2];
    const float* blk_b1  = (const float*)d_in[3];
    const float* blk_nw  = (const float*)d_in[4];
    const float* blk_nb  = (const float*)d_in[5];
    const float* blk_w2  = (const float*)d_in[6];
    const float* blk_b2  = (const float*)d_in[7];
    const float* fuse_w  = (const float*)d_in[8];
    const float* fuse_b  = (const float*)d_in[9];
    const float* gw0     = (const float*)d_in[10];
    const float* gb0     = (const float*)d_in[11];
    const float* gw1     = (const float*)d_in[12];
    const float* gb1     = (const float*)d_in[13];
    const float* ew1     = (const float*)d_in[14];
    const float* eb1     = (const float*)d_in[15];
    const float* ew2     = (const float*)d_in[16];
    const float* eb2     = (const float*)d_in[17];
    float* out = (float*)d_out;
    float* cof_out = ((size_t)out_size >= BS + Bsz*4) ? out + BS : nullptr;

    float *x1, *x2, *y1, *y2, *rb, *sb, *xf, *hb, *gv, *cofsel; int* sel;
    void* p;
    cudaGetSymbolAddress(&p, g_x1);  x1 = (float*)p;
    cudaGetSymbolAddress(&p, g_x2);  x2 = (float*)p;
    cudaGetSymbolAddress(&p, g_y1);  y1 = (float*)p;
    cudaGetSymbolAddress(&p, g_y2);  y2 = (float*)p;
    cudaGetSymbolAddress(&p, g_rb);  rb = (float*)p;
    cudaGetSymbolAddress(&p, g_sb);  sb = (float*)p;
    cudaGetSymbolAddress(&p, g_xf);  xf = (float*)p;
    cudaGetSymbolAddress(&p, g_hb);  hb = (float*)p;
    cudaGetSymbolAddress(&p, g_gv);  gv = (float*)p;
    cudaGetSymbolAddress(&p, g_sel); sel = (int*)p;
    cudaGetSymbolAddress(&p, g_cofsel); cofsel = (float*)p;

    dim3 cgrid(HWd/CTW, HWd/CTH, Bsz);   // 8 x 16 x 8
    dim3 wgrid(NPIX/128, 2, Bsz);        // winv: N=128 -> 2 oc-blocks of 64
    dim3 fgrid(NPIX/128, 1, Bsz);        // fuse: N=64

    // z = winv @ x -> x1, x2
    gemm1x1_mma<128><<<wgrid, 256>>>(x, nullptr, winv, nullptr, x1, x2);

    // hin0(x2) -> y1
    conv3x3_mma<0><<<cgrid, 256>>>(x2, blk_w1 + 0*CWS, blk_b1 + 0*64, rb,
                                   nullptr, nullptr, nullptr, nullptr, nullptr, 0, 0);
    inorm_k<<<Bsz*32, 256>>>(rb, blk_nw + 0*32, blk_nb + 0*32);
    conv3x3_mma<1><<<cgrid, 256>>>(rb, blk_w2 + 0*CWS, blk_b2 + 0*64, y1,
                                   x2, x1, nullptr, nullptr, nullptr, 0, 0);

    // hin2(y1) -> s_pre
    conv3x3_mma<0><<<cgrid, 256>>>(y1, blk_w1 + 2*CWS, blk_b1 + 2*64, rb,
                                   nullptr, nullptr, nullptr, nullptr, nullptr, 0, 0);
    inorm_k<<<Bsz*32, 256>>>(rb, blk_nw + 2*32, blk_nb + 2*32);
    conv3x3_mma<2><<<cgrid, 256>>>(rb, blk_w2 + 2*CWS, blk_b2 + 2*64, sb,
                                   y1, nullptr, nullptr, nullptr, nullptr, 0, 0);

    // hin1(y1) fused with flow -> y2
    conv3x3_mma<0><<<cgrid, 256>>>(y1, blk_w1 + 1*CWS, blk_b1 + 1*64, rb,
                                   nullptr, nullptr, nullptr, nullptr, nullptr, 0, 0);
    inorm_k<<<Bsz*32, 256>>>(rb, blk_nw + 1*32, blk_nb + 1*32);
    conv3x3_mma<3><<<cgrid, 256>>>(rb, blk_w2 + 1*CWS, blk_b2 + 1*64, y2,
                                   y1, x2, sb, nullptr, nullptr, 0, 0);

    // fuse 1x1 on concat(y1, y2)
    gemm1x1_mma<128><<<fgrid, 256>>>(y1, y2, fuse_w, fuse_b, xf, nullptr);

    // gating
    pool_k<<<Bsz*64, 256>>>(xf, gv);
    gate_k<<<1, 32>>>(gv, gw0, gb0, gw1, gb1, cof_out, sel, cofsel);

    // experts (K=2 selected per batch)
    for (int slot = 0; slot < 2; slot++) {
        conv3x3_mma<4><<<cgrid, 256>>>(xf, ew1, eb1, hb,
                                       nullptr, nullptr, nullptr, sel, cofsel, slot, 0);
        conv3x3_mma<5><<<cgrid, 256>>>(hb, ew2, eb2, out,
                                       xf, nullptr, nullptr, sel, cofsel, slot, slot);
    }
}

// round 5
// speedup vs baseline: 3.6283x; 1.2700x over previous
#include <cuda_runtime.h>
#include <math.h>

#define Bsz 8
#define Cc 64
#define HWd 128
#define NPIX (HWd*HWd)
#define PLANE ((size_t)Cc*NPIX)
#define BS ((size_t)Bsz*Cc*NPIX)
#define LEAKv 0.2f
#define CLAMPv 0.8f
#define EPSv 1e-5f
#define CWS (64*64*9)

#define CTW 16
#define CTH 8
#define INC 18
#define INREAL (10*INC)       // 180
#define INPAD 196             // uint2 stride, 196 % 16 == 4
#define WPAD 68               // 68 % 16 == 4

// ---------------- scratch ----------------
__device__ float g_x1[Bsz*Cc*NPIX];
__device__ float g_x2[Bsz*Cc*NPIX];
__device__ float g_y1[Bsz*Cc*NPIX];
__device__ float g_y2[Bsz*Cc*NPIX];
__device__ float g_rb[Bsz*Cc*NPIX];
__device__ float g_sb[Bsz*Cc*NPIX];
__device__ float g_xf[Bsz*Cc*NPIX];
__device__ float g_hb[Bsz*Cc*NPIX];
__device__ float g_gv[Bsz*Cc];
__device__ int   g_sel[Bsz*2];
__device__ float g_cofsel[Bsz*2];

__device__ __forceinline__ unsigned f2tf32(float f) {
    unsigned r;
    asm("cvt.rna.tf32.f32 %0, %1;" : "=r"(r) : "f"(f));
    return r;
}

__device__ __forceinline__ void mma_tf32(float* d, const unsigned* a, const unsigned* b) {
    asm volatile(
        "mma.sync.aligned.m16n8k8.row.col.f32.tf32.tf32.f32 "
        "{%0,%1,%2,%3}, {%4,%5,%6,%7}, {%8,%9}, {%0,%1,%2,%3};"
        : "+f"(d[0]), "+f"(d[1]), "+f"(d[2]), "+f"(d[3])
        : "r"(a[0]), "r"(a[1]), "r"(a[2]), "r"(a[3]), "r"(b[0]), "r"(b[1]));
}

// ---------------- 3x3 conv via TF32 MMA, hoisted indices + reg prefetch ----------------
template<int MODE>
__global__ __launch_bounds__(256)
void conv3x3_mma(const float* __restrict__ in, const float* __restrict__ wts,
                 const float* __restrict__ bias, float* __restrict__ out,
                 const float* __restrict__ add1, const float* __restrict__ add2,
                 const float* __restrict__ spre,
                 const int* __restrict__ sel, const float* __restrict__ cofsel,
                 int slot, int accum)
{
    __shared__ uint2 s_in[4 * INPAD];
    __shared__ uint2 s_w[36 * WPAD];

    int tid = threadIdx.x;
    int wid = tid >> 5;
    int lane = tid & 31;
    int l4 = lane & 3;
    int g  = lane >> 2;
    int warp_m = wid & 3;
    int warp_n = wid >> 2;
    int wm2 = warp_m * 2;
    int n0 = warp_n * 32;

    int b  = blockIdx.z;
    int w0 = blockIdx.x * CTW;
    int h0 = blockIdx.y * CTH;

    const float* wbase = wts;
    const float* bbase = bias;
    float cw = 1.f;
    if (MODE == 4 || MODE == 5) {
        int e = sel[b*2 + slot];
        wbase = wts + (size_t)e * CWS;
        bbase = bias + e * Cc;
        if (MODE == 5) cw = cofsel[b*2 + slot];
    }
    const float* inb = in + (size_t)b * PLANE;

    // -------- hoisted per-thread fill-slot geometry --------
    // input: 720 elements over 256 threads -> slots 0,1 full, slot 2 if tid<208
    bool iact[3];
    bool ival[3];
    unsigned ioff[3];   // element offset into inb at ch=0 (valid only if ival)
    int ismem[3];
    #pragma unroll
    for (int t = 0; t < 3; t++) {
        int i = tid + t*256;
        iact[t] = (i < 4*INREAL);
        int kq  = i / INREAL;
        int rem = i - kq*INREAL;
        int rr = rem / INC;
        int cc = rem - rr*INC;
        int h = h0 - 1 + rr;
        int w = w0 - 1 + cc;
        ival[t] = iact[t] && ((unsigned)h < HWd) && ((unsigned)w < HWd);
        ismem[t] = kq*INPAD + rem;
        ioff[t] = ival[t] ? (unsigned)(kq*NPIX + h*HWd + w) : 0u;
    }
    // weights: 36*64 = 2304 = 9*256 exactly
    unsigned woff[9];   // element offset into wbase at ch=0
    int wsm[9];
    #pragma unroll
    for (int t = 0; t < 9; t++) {
        int i = tid + t*256;
        int q  = i % 36;
        int oc = i / 36;
        int kq = q & 3;
        int tap = q >> 2;
        wsm[t] = q*WPAD + oc;
        woff[t] = (unsigned)((oc*Cc + kq)*9 + tap);
    }

    float d[2][4][4];
    #pragma unroll
    for (int mt = 0; mt < 2; mt++)
        #pragma unroll
        for (int nt = 0; nt < 4; nt++)
            #pragma unroll
            for (int r = 0; r < 4; r++) d[mt][nt][r] = 0.f;

    // prefetch registers
    float ipf0[3], ipf1[3];
    float wpf0[9], wpf1[9];

    // load chunk 0
    #pragma unroll
    for (int t = 0; t < 3; t++) {
        ipf0[t] = ival[t] ? inb[ioff[t]] : 0.f;
        ipf1[t] = ival[t] ? inb[ioff[t] + 4*NPIX] : 0.f;
    }
    #pragma unroll
    for (int t = 0; t < 9; t++) {
        wpf0[t] = wbase[woff[t]];
        wpf1[t] = wbase[woff[t] + 36];
    }

    #pragma unroll 1
    for (int ck = 0; ck < 8; ck++) {
        __syncthreads();   // previous MMA phase done reading smem
        // store current chunk (cvt at store time)
        #pragma unroll
        for (int t = 0; t < 3; t++)
            if (iact[t]) s_in[ismem[t]] = make_uint2(f2tf32(ipf0[t]), f2tf32(ipf1[t]));
        #pragma unroll
        for (int t = 0; t < 9; t++)
            s_w[wsm[t]] = make_uint2(f2tf32(wpf0[t]), f2tf32(wpf1[t]));
        // issue next chunk's loads (overlap with MMA below)
        if (ck < 7) {
            unsigned ib = (unsigned)((ck+1) * 8*NPIX);
            #pragma unroll
            for (int t = 0; t < 3; t++) {
                if (ival[t]) {
                    ipf0[t] = inb[ioff[t] + ib];
                    ipf1[t] = inb[ioff[t] + ib + 4*NPIX];
                }
            }
            unsigned wb = (unsigned)((ck+1) * 72);
            #pragma unroll
            for (int t = 0; t < 9; t++) {
                wpf0[t] = wbase[woff[t] + wb];
                wpf1[t] = wbase[woff[t] + wb + 36];
            }
        }
        __syncthreads();

        #pragma unroll
        for (int tap = 0; tap < 9; tap++) {
            int ky = tap / 3, kx = tap % 3;
            int abase = l4*INPAD + (wm2 + ky)*INC + kx + g;
            unsigned a[2][4];
            #pragma unroll
            for (int mt = 0; mt < 2; mt++) {
                uint2 p0 = s_in[abase + mt*INC];
                uint2 p1 = s_in[abase + mt*INC + 8];
                a[mt][0] = p0.x; a[mt][1] = p1.x; a[mt][2] = p0.y; a[mt][3] = p1.y;
            }
            int bb = (tap*4 + l4)*WPAD + n0 + g;
            unsigned bq[4][2];
            #pragma unroll
            for (int nt = 0; nt < 4; nt++) {
                uint2 q = s_w[bb + nt*8];
                bq[nt][0] = q.x; bq[nt][1] = q.y;
            }
            #pragma unroll
            for (int mt = 0; mt < 2; mt++)
                #pragma unroll
                for (int nt = 0; nt < 4; nt++)
                    mma_tf32(d[mt][nt], a[mt], bq[nt]);
        }
    }

    // epilogue
    #pragma unroll
    for (int mt = 0; mt < 2; mt++) {
        int h = h0 + wm2 + mt;
        #pragma unroll
        for (int nt = 0; nt < 4; nt++) {
            int oc = n0 + nt*8 + l4*2;
            float bv0 = bbase[oc], bv1 = bbase[oc+1];
            size_t p0 = (size_t)b*PLANE + (size_t)oc*NPIX + (size_t)h*HWd;
            size_t p1 = p0 + NPIX;
            int wa = w0 + g, wb2 = wa + 8;
            float vv[4] = { d[mt][nt][0] + bv0, d[mt][nt][1] + bv1,
                            d[mt][nt][2] + bv0, d[mt][nt][3] + bv1 };
            size_t ix[4] = { p0 + wa, p1 + wa, p0 + wb2, p1 + wb2 };
            #pragma unroll
            for (int r = 0; r < 4; r++) {
                size_t idx = ix[r];
                float v = vv[r];
                if (MODE == 1) {
                    v += add1[idx] + add2[idx];
                } else if (MODE == 2) {
                    v += add1[idx];
                } else if (MODE == 3) {
                    float sp = spre[idx];
                    float sig = 1.f / (1.f + expf(-sp));
                    float s = CLAMPv * (2.f*sig - 1.f);
                    v += add1[idx] + add2[idx] * expf(s);
                } else if (MODE == 4) {
                    v = v > 0.f ? v : LEAKv * v;
                } else if (MODE == 5) {
                    v = (v + add1[idx]) * cw;
                    if (accum) v += out[idx];
                }
                out[idx] = v;
            }
        }
    }
}

// ---------------- 1x1 GEMM via TF32 MMA ----------------
#define GPAD 132

template<int IC>
__global__ __launch_bounds__(256)
void gemm1x1_mma(const float* __restrict__ inA, const float* __restrict__ inB,
                 const float* __restrict__ W, const float* __restrict__ bias,
                 float* __restrict__ outA, float* __restrict__ outB)
{
    __shared__ uint2 s_x[8 * GPAD];
    __shared__ uint2 s_w[8 * WPAD];

    int tid = threadIdx.x;
    int wid = tid >> 5;
    int lane = tid & 31;
    int l4 = lane & 3;
    int g  = lane >> 2;
    int warp_m = wid & 3;
    int warp_n = wid >> 2;
    int n0 = warp_n * 32;

    int b   = blockIdx.z;
    int oc0 = blockIdx.y * 64;
    int p0  = blockIdx.x * 128;

    float d[2][4][4];
    #pragma unroll
    for (int mt = 0; mt < 2; mt++)
        #pragma unroll
        for (int nt = 0; nt < 4; nt++)
            #pragma unroll
            for (int r = 0; r < 4; r++) d[mt][nt][r] = 0.f;

    for (int ch = 0; ch < IC; ch += 16) {
        for (int i = tid; i < 8*128; i += 256) {
            int q = i >> 7;
            int p = i & 127;
            int ic0 = ch + (q >> 2)*8 + (q & 3);
            unsigned v0, v1;
            if (inB != nullptr) {
                const float* s0 = (ic0 < 64) ? inA : inB;
                const float* s1 = (ic0+4 < 64) ? inA : inB;
                v0 = f2tf32(s0[(size_t)b*PLANE + (size_t)(ic0 & 63)*NPIX + p0 + p]);
                v1 = f2tf32(s1[(size_t)b*PLANE + (size_t)((ic0+4) & 63)*NPIX + p0 + p]);
            } else {
                v0 = f2tf32(inA[((size_t)b*IC + ic0)*NPIX + p0 + p]);
                v1 = f2tf32(inA[((size_t)b*IC + ic0 + 4)*NPIX + p0 + p]);
            }
            s_x[q*GPAD + p] = make_uint2(v0, v1);
        }
        for (int i = tid; i < 8*64; i += 256) {
            int q  = i & 7;
            int oc = i >> 3;
            int ic0 = ch + (q >> 2)*8 + (q & 3);
            size_t o = (size_t)(oc0 + oc)*IC + ic0;
            s_w[q*WPAD + oc] = make_uint2(f2tf32(W[o]), f2tf32(W[o + 4]));
        }
        __syncthreads();

        #pragma unroll
        for (int ks = 0; ks < 2; ks++) {
            int abase = (ks*4 + l4)*GPAD + warp_m*32 + g;
            unsigned a[2][4];
            #pragma unroll
            for (int mt = 0; mt < 2; mt++) {
                uint2 q0 = s_x[abase + mt*16];
                uint2 q1 = s_x[abase + mt*16 + 8];
                a[mt][0] = q0.x; a[mt][1] = q1.x; a[mt][2] = q0.y; a[mt][3] = q1.y;
            }
            int bb = (ks*4 + l4)*WPAD + n0 + g;
            unsigned bq[4][2];
            #pragma unroll
            for (int nt = 0; nt < 4; nt++) {
                uint2 q = s_w[bb + nt*8];
                bq[nt][0] = q.x; bq[nt][1] = q.y;
            }
            #pragma unroll
            for (int mt = 0; mt < 2; mt++)
                #pragma unroll
                for (int nt = 0; nt < 4; nt++)
                    mma_tf32(d[mt][nt], a[mt], bq[nt]);
        }
        __syncthreads();
    }

    #pragma unroll
    for (int mt = 0; mt < 2; mt++) {
        #pragma unroll
        for (int nt = 0; nt < 4; nt++) {
            int oc = oc0 + n0 + nt*8 + l4*2;
            float bv0 = bias ? bias[oc] : 0.f;
            float bv1 = bias ? bias[oc+1] : 0.f;
            float* dst = outA;
            int ocd = oc;
            if (outB != nullptr && oc >= 64) { dst = outB; ocd = oc - 64; }
            int pix = p0 + warp_m*32 + mt*16 + g;
            size_t q0 = (size_t)b*PLANE + (size_t)ocd*NPIX + pix;
            size_t q1 = q0 + NPIX;
            dst[q0]     = d[mt][nt][0] + bv0;
            dst[q1]     = d[mt][nt][1] + bv1;
            dst[q0 + 8] = d[mt][nt][2] + bv0;
            dst[q1 + 8] = d[mt][nt][3] + bv1;
        }
    }
}

// ---------------- instance norm ----------------
__global__ __launch_bounds__(256)
void inorm_k(float* __restrict__ r, const float* __restrict__ nw, const float* __restrict__ nb)
{
    int bidx = blockIdx.x;
    int b = bidx >> 5, c = bidx & 31;
    float* p = r + (size_t)b*PLANE + (size_t)c*NPIX;
    int tid = threadIdx.x;
    float s = 0.f, s2 = 0.f;
    for (int i = tid; i < NPIX; i += 256) { float v = p[i]; s += v; s2 += v*v; }
    __shared__ float sh[256], sh2[256];
    sh[tid] = s; sh2[tid] = s2;
    __syncthreads();
    for (int st = 128; st; st >>= 1) {
        if (tid < st) { sh[tid] += sh[tid+st]; sh2[tid] += sh2[tid+st]; }
        __syncthreads();
    }
    float mean = sh[0] * (1.f/NPIX);
    float var = sh2[0] * (1.f/NPIX) - mean*mean;
    float inv = rsqrtf(var + EPSv);
    float ga = nw[c], be = nb[c];
    for (int i = tid; i < NPIX; i += 256)
        p[i] = (p[i] - mean) * inv * ga + be;
}

// ---------------- pool ----------------
__global__ __launch_bounds__(256)
void pool_k(const float* __restrict__ xf, float* __restrict__ g)
{
    int bc = blockIdx.x;
    const float* p = xf + (size_t)bc * NPIX;
    int tid = threadIdx.x;
    float mx = -1e30f, sm = 0.f;
    for (int i = tid; i < NPIX; i += 256) { float v = p[i]; mx = fmaxf(mx, v); sm += v; }
    __shared__ float smx[256], ssm[256];
    smx[tid] = mx; ssm[tid] = sm;
    __syncthreads();
    for (int st = 128; st; st >>= 1) {
        if (tid < st) { smx[tid] = fmaxf(smx[tid], smx[tid+st]); ssm[tid] += ssm[tid+st]; }
        __syncthreads();
    }
    if (tid == 0) g[bc] = smx[0] + ssm[0] * (1.f/NPIX);
}

// ---------------- gating ----------------
__global__ void gate_k(const float* __restrict__ g,
                       const float* __restrict__ gw0, const float* __restrict__ gb0,
                       const float* __restrict__ gw1, const float* __restrict__ gb1,
                       float* __restrict__ cof_out, int* __restrict__ sel,
                       float* __restrict__ cofsel)
{
    int b = threadIdx.x;
    if (b >= Bsz) return;
    float lg[4], noi[4];
    for (int e = 0; e < 4; e++) {
        float a0 = gb0[e], a1 = gb1[e];
        for (int c = 0; c < 64; c++) {
            float gv = g[b*64 + c];
            a0 += gw0[e*64 + c] * gv;
            a1 += gw1[e*64 + c] * gv;
        }
        lg[e] = a1 > 0.f ? a1 : LEAKv * a1;
        noi[e] = fmaxf(a0, 0.f) + log1pf(expf(-fabsf(a0)));
    }
    float m = 0.25f * (noi[0] + noi[1] + noi[2] + noi[3]);
    float var = 0.f;
    for (int e = 0; e < 4; e++) { float dd = noi[e] - m; var += dd*dd; }
    float sd = sqrtf(var / 3.f);
    float sc[4];
    for (int e = 0; e < 4; e++) sc[e] = lg[e] + (noi[e] - m) / sd;
    int i0 = 0;
    for (int e = 1; e < 4; e++) if (sc[e] > sc[i0]) i0 = e;
    int i1 = -1;
    for (int e = 0; e < 4; e++) {
        if (e == i0) continue;
        if (i1 < 0 || sc[e] > sc[i1]) i1 = e;
    }
    float mm = fmaxf(lg[i0], lg[i1]);
    float e0 = expf(lg[i0] - mm), e1 = expf(lg[i1] - mm);
    float c0 = e0 / (e0 + e1), c1 = e1 / (e0 + e1);
    if (cof_out) {
        for (int e = 0; e < 4; e++) cof_out[b*4 + e] = 0.f;
        cof_out[b*4 + i0] = c0;
        cof_out[b*4 + i1] = c1;
    }
    sel[b*2 + 0] = i0; sel[b*2 + 1] = i1;
    cofsel[b*2 + 0] = c0; cofsel[b*2 + 1] = c1;
}

// ---------------- launch ----------------
extern "C" void kernel_launch(void* const* d_in, const int* in_sizes, int n_in,
                              void* d_out, int out_size)
{
    const float* x       = (const float*)d_in[0];
    const float* winv    = (const float*)d_in[1];
    const float* blk_w1  = (const float*)d_in[2];
    const float* blk_b1  = (const float*)d_in[3];
    const float* blk_nw  = (const float*)d_in[4];
    const float* blk_nb  = (const float*)d_in[5];
    const float* blk_w2  = (const float*)d_in[6];
    const float* blk_b2  = (const float*)d_in[7];
    const float* fuse_w  = (const float*)d_in[8];
    const float* fuse_b  = (const float*)d_in[9];
    const float* gw0     = (const float*)d_in[10];
    const float* gb0     = (const float*)d_in[11];
    const float* gw1     = (const float*)d_in[12];
    const float* gb1     = (const float*)d_in[13];
    const float* ew1     = (const float*)d_in[14];
    const float* eb1     = (const float*)d_in[15];
    const float* ew2     = (const float*)d_in[16];
    const float* eb2     = (const float*)d_in[17];
    float* out = (float*)d_out;
    float* cof_out = ((size_t)out_size >= BS + Bsz*4) ? out + BS : nullptr;

    float *x1, *x2, *y1, *y2, *rb, *sb, *xf, *hb, *gv, *cofsel; int* sel;
    void* p;
    cudaGetSymbolAddress(&p, g_x1);  x1 = (float*)p;
    cudaGetSymbolAddress(&p, g_x2);  x2 = (float*)p;
    cudaGetSymbolAddress(&p, g_y1);  y1 = (float*)p;
    cudaGetSymbolAddress(&p, g_y2);  y2 = (float*)p;
    cudaGetSymbolAddress(&p, g_rb);  rb = (float*)p;
    cudaGetSymbolAddress(&p, g_sb);  sb = (float*)p;
    cudaGetSymbolAddress(&p, g_xf);  xf = (float*)p;
    cudaGetSymbolAddress(&p, g_hb);  hb = (float*)p;
    cudaGetSymbolAddress(&p, g_gv);  gv = (float*)p;
    cudaGetSymbolAddress(&p, g_sel); sel = (int*)p;
    cudaGetSymbolAddress(&p, g_cofsel); cofsel = (float*)p;

    dim3 cgrid(HWd/CTW, HWd/CTH, Bsz);
    dim3 wgrid(NPIX/128, 2, Bsz);
    dim3 fgrid(NPIX/128, 1, Bsz);

    gemm1x1_mma<128><<<wgrid, 256>>>(x, nullptr, winv, nullptr, x1, x2);

    conv3x3_mma<0><<<cgrid, 256>>>(x2, blk_w1 + 0*CWS, blk_b1 + 0*64, rb,
                                   nullptr, nullptr, nullptr, nullptr, nullptr, 0, 0);
    inorm_k<<<Bsz*32, 256>>>(rb, blk_nw + 0*32, blk_nb + 0*32);
    conv3x3_mma<1><<<cgrid, 256>>>(rb, blk_w2 + 0*CWS, blk_b2 + 0*64, y1,
                                   x2, x1, nullptr, nullptr, nullptr, 0, 0);

    conv3x3_mma<0><<<cgrid, 256>>>(y1, blk_w1 + 2*CWS, blk_b1 + 2*64, rb,
                                   nullptr, nullptr, nullptr, nullptr, nullptr, 0, 0);
    inorm_k<<<Bsz*32, 256>>>(rb, blk_nw + 2*32, blk_nb + 2*32);
    conv3x3_mma<2><<<cgrid, 256>>>(rb, blk_w2 + 2*CWS, blk_b2 + 2*64, sb,
                                   y1, nullptr, nullptr, nullptr, nullptr, 0, 0);

    conv3x3_mma<0><<<cgrid, 256>>>(y1, blk_w1 + 1*CWS, blk_b1 + 1*64, rb,
                                   nullptr, nullptr, nullptr, nullptr, nullptr, 0, 0);
    inorm_k<<<Bsz*32, 256>>>(rb, blk_nw + 1*32, blk_nb + 1*32);
    conv3x3_mma<3><<<cgrid, 256>>>(rb, blk_w2 + 1*CWS, blk_b2 + 1*64, y2,
                                   y1, x2, sb, nullptr, nullptr, 0, 0);

    gemm1x1_mma<128><<<fgrid, 256>>>(y1, y2, fuse_w, fuse_b, xf, nullptr);

    pool_k<<<Bsz*64, 256>>>(xf, gv);
    gate_k<<<1, 32>>>(gv, gw0, gb0, gw1, gb1, cof_out, sel, cofsel);

    for (int slot = 0; slot < 2; slot++) {
        conv3x3_mma<4><<<cgrid, 256>>>(xf, ew1, eb1, hb,
                                       nullptr, nullptr, nullptr, sel, cofsel, slot, 0);
        conv3x3_mma<5><<<cgrid, 256>>>(hb, ew2, eb2, out,
                                       xf, nullptr, nullptr, sel, cofsel, slot, slot);
    }
}